// round 1
// baseline (speedup 1.0000x reference)
#include <cuda_runtime.h>
#include <cuda_bf16.h>

// ModuleWithRouting: out[row] = x[row] if expert0 in top-2 of x[row][0..7], else 0.
// Selection condition: count(x[row][j] > x[row][0]) < 2  (ties prefer lower index).
// Pure HBM streaming: 32B read + 32B write per row.

static constexpr int EXPERTS = 8;

__global__ void __launch_bounds__(256)
routing_e0_kernel(const float4* __restrict__ in, float4* __restrict__ out, int nrows)
{
    int row = blockIdx.x * blockDim.x + threadIdx.x;
    if (row >= nrows) return;

    // Each row = 8 floats = two float4's.
    float4 a = __ldg(&in[2 * row + 0]);
    float4 b = __ldg(&in[2 * row + 1]);

    float x0 = a.x;
    int gt = (a.y > x0) + (a.z > x0) + (a.w > x0)
           + (b.x > x0) + (b.y > x0) + (b.z > x0) + (b.w > x0);

    if (gt >= 2) {
        a = make_float4(0.f, 0.f, 0.f, 0.f);
        b = a;
    }

    out[2 * row + 0] = a;
    out[2 * row + 1] = b;
}

extern "C" void kernel_launch(void* const* d_in, const int* in_sizes, int n_in,
                              void* d_out, int out_size)
{
    const float4* in = (const float4*)d_in[0];
    float4* out = (float4*)d_out;
    int nrows = in_sizes[0] / EXPERTS;   // 4194304

    int threads = 256;
    int blocks = (nrows + threads - 1) / threads;
    routing_e0_kernel<<<blocks, threads>>>(in, out, nrows);
}